// round 3
// baseline (speedup 1.0000x reference)
#include <cuda_runtime.h>
#include <cuda_fp16.h>
#include <cstdint>
#include <math.h>

// ---------------- problem constants ----------------
static constexpr int BATCH  = 64;
static constexpr int NA     = 8192;
static constexpr int NB     = 8192;
static constexpr int TILE_N = 128;                 // mask columns per CTA
static constexpr int TILE_K = 128;                 // mask rows per chunk
static constexpr int KSPLIT = 2;                   // 64 x 2 = 128 CTAs
static constexpr int CHUNKS = NA / TILE_K / KSPLIT;  // 32

// SMEM tiles, padded pitch 136 halves = 272 B (17 x 16B -> conflict-free LDSM)
static constexpr int PITCH_H  = 136;
static constexpr int PITCH_B  = PITCH_H * 2;       // 272
static constexpr int TILE_BYTES = 128 * PITCH_B;   // 34816
static constexpr int STAGE    = 2 * TILE_BYTES;    // A + B = 69632
static constexpr int ACC_OFF  = 2 * STAGE;         // 139264
static constexpr int SMEM_BYTES = ACC_OFF + 1024;  // + real_s/imag_s

static constexpr int CB_PITCH = 132;               // floats, 8B-aligned float2, bank-spread

// ---------------- device scratch ----------------
__device__ __half  g_A[2 * BATCH * NA];   // rows 0..63 = cos(a), 64..127 = sin(a); K-major
__device__ float   g_cb[BATCH * NB];
__device__ float   g_sb[BATCH * NB];
__device__ float   g_real[BATCH];
__device__ float   g_imag[BATCH];
__device__ unsigned int g_npairs;

// ---------------- helpers ----------------
__device__ __forceinline__ uint32_t smem_u32(const void* p) {
    uint32_t a;
    asm("{ .reg .u64 t; cvta.to.shared.u64 t, %1; cvt.u32.u64 %0, t; }" : "=r"(a) : "l"(p));
    return a;
}

__device__ __forceinline__ void cp_async16(uint32_t s, const void* g) {
    asm volatile("cp.async.cg.shared.global [%0], [%1], 16;" :: "r"(s), "l"(g) : "memory");
}
#define CP_COMMIT()  asm volatile("cp.async.commit_group;" ::: "memory")
#define CP_WAIT0()   asm volatile("cp.async.wait_group 0;" ::: "memory")

#define LDSM_X4(r, addr) \
    asm volatile("ldmatrix.sync.aligned.m8n8.x4.shared.b16 {%0,%1,%2,%3}, [%4];" \
        : "=r"((r)[0]), "=r"((r)[1]), "=r"((r)[2]), "=r"((r)[3]) : "r"(addr))

#define LDSM_X4_T(r, addr) \
    asm volatile("ldmatrix.sync.aligned.m8n8.x4.trans.shared.b16 {%0,%1,%2,%3}, [%4];" \
        : "=r"((r)[0]), "=r"((r)[1]), "=r"((r)[2]), "=r"((r)[3]) : "r"(addr))

__device__ __forceinline__ void mma_16816(float* d, const uint32_t* a, const uint32_t* b) {
    asm volatile(
        "mma.sync.aligned.m16n8k16.row.col.f32.f16.f16.f32 "
        "{%0,%1,%2,%3}, {%4,%5,%6,%7}, {%8,%9}, {%0,%1,%2,%3};"
        : "+f"(d[0]), "+f"(d[1]), "+f"(d[2]), "+f"(d[3])
        : "r"(a[0]), "r"(a[1]), "r"(a[2]), "r"(a[3]), "r"(b[0]), "r"(b[1]));
}

// ---------------- prep: cos/sin + zero accumulators ----------------
__global__ void plv_prep(const float* __restrict__ pa, const float* __restrict__ pb) {
    int idx = blockIdx.x * blockDim.x + threadIdx.x;
    if (idx < BATCH * NA) {
        float s, c;
        sincosf(pa[idx], &s, &c);
        int b = idx >> 13;
        int k = idx & (NA - 1);
        g_A[(size_t)b * NA + k]        = __float2half_rn(c);
        g_A[(size_t)(b + 64) * NA + k] = __float2half_rn(s);
        sincosf(pb[idx], &s, &c);
        g_cb[idx] = c;
        g_sb[idx] = s;
    }
    if (blockIdx.x == 0) {
        if (threadIdx.x < BATCH) { g_real[threadIdx.x] = 0.0f; g_imag[threadIdx.x] = 0.0f; }
        if (threadIdx.x == BATCH) g_npairs = 0u;
    }
}

// ---------------- main: fused mask-stream HMMA GEMM + epilogue ----------------
__global__ void __launch_bounds__(256, 1) plv_main(const int* __restrict__ mask) {
    extern __shared__ char smem_raw[];
    const uint32_t sb = smem_u32(smem_raw);

    const int tid  = threadIdx.x;
    const int wid  = tid >> 5;
    const int lane = tid & 31;
    const int wm   = wid >> 1;     // 0..3 : warp row (32 m each)
    const int wn   = wid & 1;      // 0..1 : warp col (64 n each)
    const int j0   = blockIdx.x * TILE_N;
    const long long kbase = (long long)blockIdx.y * (NA / KSPLIT);

    float acc[2][8][4];
#pragma unroll
    for (int i = 0; i < 2; ++i)
#pragma unroll
        for (int j = 0; j < 8; ++j)
#pragma unroll
            for (int r = 0; r < 4; ++r) acc[i][j][r] = 0.0f;

    unsigned int msum = 0;

    // lane addressing for ldmatrix (4 8x8 matrices)
    const uint32_t lrow = (uint32_t)(lane & 15);
    const uint32_t lhi  = (uint32_t)(lane >> 4);

    // ---- A loader (cp.async, fp16 straight from gmem) ----
    auto load_A = [&](int chunk, int s) {
        const long long k0 = kbase + (long long)chunk * TILE_K;
        const uint32_t dstBase = sb + (uint32_t)s * STAGE;
#pragma unroll
        for (int it = 0; it < 8; ++it) {
            const int idx = tid + it * 256;
            const int m = idx >> 4;
            const int g = idx & 15;
            cp_async16(dstBase + (uint32_t)m * PITCH_B + (uint32_t)g * 16,
                       (const char*)g_A + ((size_t)m * NA + (size_t)k0 + (size_t)g * 8) * 2);
        }
        CP_COMMIT();
    };

    // ---- B loader: 16 x LDG.128 into regs (held during compute) ----
    uint4 breg[16];
    auto load_B = [&](int chunk) {
        const long long k0 = kbase + (long long)chunk * TILE_K;
        const int* base = mask + (size_t)k0 * NB + j0;
#pragma unroll
        for (int it = 0; it < 16; ++it) {
            const int idx = tid + it * 256;
            const int k = idx >> 5;
            const int n = (idx & 31) * 4;
            breg[it] = *reinterpret_cast<const uint4*>(base + (size_t)k * NB + n);
        }
    };

    // ---- B convert + STS (stage s): [k][n] fp16 ----
    auto store_B = [&](int s) {
        const uint32_t dstBase = sb + (uint32_t)s * STAGE + TILE_BYTES;
#pragma unroll
        for (int it = 0; it < 16; ++it) {
            const int idx = tid + it * 256;
            const int k = idx >> 5;
            const int n = (idx & 31) * 4;
            const uint4 v = breg[it];
            msum += v.x + v.y + v.z + v.w;
            const uint32_t p0 = (v.x * 0x3C00u) | ((v.y * 0x3C00u) << 16);
            const uint32_t p1 = (v.z * 0x3C00u) | ((v.w * 0x3C00u) << 16);
            asm volatile("st.shared.v2.b32 [%0], {%1, %2};"
                :: "r"(dstBase + (uint32_t)k * PITCH_B + (uint32_t)n * 2), "r"(p0), "r"(p1)
                : "memory");
        }
    };

    // ---- compute one chunk from stage s ----
    auto compute = [&](int s) {
        const uint32_t aBase = sb + (uint32_t)s * STAGE + (uint32_t)(wm * 32) * PITCH_B
                             + lrow * PITCH_B + lhi * 16;
        const uint32_t bBase = sb + (uint32_t)s * STAGE + TILE_BYTES + (uint32_t)(wn * 64) * 2
                             + lrow * PITCH_B + lhi * 16;
#pragma unroll
        for (int ks = 0; ks < 8; ++ks) {
            uint32_t afr[2][4];
            LDSM_X4(afr[0], aBase + (uint32_t)ks * 32);
            LDSM_X4(afr[1], aBase + 16u * PITCH_B + (uint32_t)ks * 32);
            uint32_t bfr[4][4];
#pragma unroll
            for (int nj = 0; nj < 4; ++nj)
                LDSM_X4_T(bfr[nj], bBase + (uint32_t)ks * 16 * PITCH_B + (uint32_t)nj * 32);
#pragma unroll
            for (int mi = 0; mi < 2; ++mi)
#pragma unroll
                for (int nj = 0; nj < 4; ++nj) {
                    mma_16816(acc[mi][nj * 2 + 0], afr[mi], &bfr[nj][0]);
                    mma_16816(acc[mi][nj * 2 + 1], afr[mi], &bfr[nj][2]);
                }
        }
    };

    // ---- pre-loop: fill stage 0 ----
    load_A(0, 0);
    load_B(0);
    store_B(0);
    CP_WAIT0();
    __syncthreads();

    // ---- main loop ----
    for (int c = 0; c < CHUNKS; ++c) {
        const int s = c & 1;
        if (c + 1 < CHUNKS) {
            load_B(c + 1);          // LDGs in flight during compute
            load_A(c + 1, s ^ 1);
        }
        compute(s);
        if (c + 1 < CHUNKS) {
            store_B(s ^ 1);
            CP_WAIT0();
        }
        __syncthreads();
    }

    // ---- n_pairs reduce ----
#pragma unroll
    for (int o = 16; o; o >>= 1) msum += __shfl_down_sync(0xFFFFFFFFu, msum, o);
    if (lane == 0) atomicAdd(&g_npairs, msum);

    // ---- epilogue ----
    float* cbs    = reinterpret_cast<float*>(smem_raw);            // 64 x CB_PITCH
    float* sbs    = cbs + 64 * CB_PITCH;
    float* real_s = reinterpret_cast<float*>(smem_raw + ACC_OFF);
    float* imag_s = real_s + 64;

    if (tid < 64) { real_s[tid] = 0.0f; imag_s[tid] = 0.0f; }
#pragma unroll
    for (int it = 0; it < 32; ++it) {
        const int idx = tid + it * 256;
        const int b = idx >> 7;
        const int n = idx & 127;
        cbs[b * CB_PITCH + n] = g_cb[(size_t)b * NB + j0 + n];
        sbs[b * CB_PITCH + n] = g_sb[(size_t)b * NB + j0 + n];
    }
    __syncthreads();

    const bool isCos = (wm < 2);
    const int  tq    = lane >> 2;           // t/4
    const int  tc    = (lane & 3) * 2;      // col pair base
#pragma unroll
    for (int mi = 0; mi < 2; ++mi) {
#pragma unroll
        for (int h = 0; h < 2; ++h) {
            const int m = wm * 32 + mi * 16 + h * 8 + tq;
            const int b = m & 63;
            float racc = 0.0f, iacc = 0.0f;
#pragma unroll
            for (int ni = 0; ni < 8; ++ni) {
                const int n = wn * 64 + ni * 8 + tc;
                const float dlo = acc[mi][ni][h * 2 + 0];
                const float dhi = acc[mi][ni][h * 2 + 1];
                const float2 cv = *reinterpret_cast<const float2*>(&cbs[b * CB_PITCH + n]);
                const float2 sv = *reinterpret_cast<const float2*>(&sbs[b * CB_PITCH + n]);
                if (isCos) {
                    racc = fmaf(dlo, cv.x, fmaf(dhi, cv.y, racc));
                    iacc = fmaf(-dlo, sv.x, fmaf(-dhi, sv.y, iacc));
                } else {
                    racc = fmaf(dlo, sv.x, fmaf(dhi, sv.y, racc));
                    iacc = fmaf(dlo, cv.x, fmaf(dhi, cv.y, iacc));
                }
            }
            atomicAdd(&real_s[b], racc);
            atomicAdd(&imag_s[b], iacc);
        }
    }
    __syncthreads();
    if (tid < 64) {
        atomicAdd(&g_real[tid], real_s[tid]);
        atomicAdd(&g_imag[tid], imag_s[tid]);
    }
}

// ---------------- final ----------------
__global__ void plv_final(float* __restrict__ out) {
    const int b = threadIdx.x;
    if (b < BATCH) {
        const float np = fmaxf((float)g_npairs, 1.0f);
        const float r = g_real[b], i = g_imag[b];
        out[b] = sqrtf(r * r + i * i) / np;
    }
}

// ---------------- launch ----------------
extern "C" void kernel_launch(void* const* d_in, const int* in_sizes, int n_in,
                              void* d_out, int out_size) {
    (void)in_sizes; (void)n_in; (void)out_size;
    const float* pa = (const float*)d_in[0];
    const float* pb = (const float*)d_in[1];
    const int* mask = (const int*)d_in[2];
    float* out      = (float*)d_out;

    cudaFuncSetAttribute(plv_main, cudaFuncAttributeMaxDynamicSharedMemorySize, SMEM_BYTES);

    plv_prep<<<(BATCH * NA + 255) / 256, 256>>>(pa, pb);
    plv_main<<<dim3(NB / TILE_N, KSPLIT), 256, SMEM_BYTES>>>(mask);
    plv_final<<<1, 64>>>(out);
}